// round 3
// baseline (speedup 1.0000x reference)
#include <cuda_runtime.h>
#include <cuda_bf16.h>

// Problem constants (shapes come from in_sizes at launch, but capacity is fixed)
#define MAX_NODES 50000
#define D 64

// Scratch (device globals; no allocation allowed)
__device__ float g_lin[MAX_NODES * D];   // data @ W_lin^T + b_lin
__device__ float g_acc[MAX_NODES * D];   // sum over incoming edges of lin[src]
__device__ float g_deg[MAX_NODES];       // incoming-edge count (float)

// ---------------------------------------------------------------------------
// Zero the accumulators (graph replays must start clean every call)
// ---------------------------------------------------------------------------
__global__ void zero_kernel(int n) {
    int total4 = (n * D) / 4;                // acc as float4
    float4* a4 = reinterpret_cast<float4*>(g_acc);
    for (int i = blockIdx.x * blockDim.x + threadIdx.x; i < total4;
         i += gridDim.x * blockDim.x) {
        a4[i] = make_float4(0.f, 0.f, 0.f, 0.f);
    }
    for (int i = blockIdx.x * blockDim.x + threadIdx.x; i < n;
         i += gridDim.x * blockDim.x) {
        g_deg[i] = 0.f;
    }
}

// ---------------------------------------------------------------------------
// C[r][c] = sum_k X[r][k] * W[c][k] + b[c]      (i.e. X @ W^T + b)
// 64x64 block tile, 4x4 register tile per thread, 256 threads.
// Shared layouts are k-major so both reads are conflict-free LDS.128.
// ---------------------------------------------------------------------------
__global__ __launch_bounds__(256) void gemm_lin_kernel(
    const float* __restrict__ X, const float* __restrict__ W,
    const float* __restrict__ b, int n) {
    __shared__ float s_x[64 * 68];   // s_x[k*68 + r]
    __shared__ float s_w[64 * 68];   // s_w[k*68 + c] = W[c][k]
    __shared__ float s_b[64];

    int t = threadIdx.x;
    int row0 = blockIdx.x * 64;

    for (int i = t; i < 64 * 64; i += 256) {
        int r = i >> 6, k = i & 63;
        int gr = row0 + r;
        s_x[k * 68 + r] = (gr < n) ? X[gr * 64 + k] : 0.f;
    }
    for (int i = t; i < 64 * 64; i += 256) {
        int c = i >> 6, k = i & 63;
        s_w[k * 68 + c] = W[c * 64 + k];
    }
    if (t < 64) s_b[t] = b[t];
    __syncthreads();

    int tx = t & 15, ty = t >> 4;
    float acc[4][4];
#pragma unroll
    for (int i = 0; i < 4; i++)
#pragma unroll
        for (int j = 0; j < 4; j++) acc[i][j] = 0.f;

#pragma unroll 8
    for (int k = 0; k < 64; k++) {
        float4 xv = *reinterpret_cast<const float4*>(&s_x[k * 68 + ty * 4]);
        float4 wv = *reinterpret_cast<const float4*>(&s_w[k * 68 + tx * 4]);
        float xs[4] = {xv.x, xv.y, xv.z, xv.w};
        float ws[4] = {wv.x, wv.y, wv.z, wv.w};
#pragma unroll
        for (int i = 0; i < 4; i++)
#pragma unroll
            for (int j = 0; j < 4; j++) acc[i][j] = fmaf(xs[i], ws[j], acc[i][j]);
    }

#pragma unroll
    for (int i = 0; i < 4; i++) {
        int gr = row0 + ty * 4 + i;
        if (gr < n) {
#pragma unroll
            for (int j = 0; j < 4; j++) {
                int c = tx * 4 + j;
                g_lin[gr * 64 + c] = acc[i][j] + s_b[c];
            }
        }
    }
}

// ---------------------------------------------------------------------------
// Edge scatter: for each edge e, acc[tgt] += lin[src]; deg[tgt] += 1.
// 4 threads per edge, each handling 16 floats via red.global.add.v4.f32.
// lin (12.8 MB) is L2-resident -> gathers are L2 hits.
// ---------------------------------------------------------------------------
__global__ __launch_bounds__(256) void scatter_kernel(
    const int* __restrict__ src, const int* __restrict__ tgt, int E) {
    int t = blockIdx.x * blockDim.x + threadIdx.x;
    int e = t >> 2;
    int p = t & 3;
    if (e >= E) return;

    int s = __ldg(&src[e]);
    int d = __ldg(&tgt[e]);

    if (p == 0) atomicAdd(&g_deg[d], 1.0f);

    const float4* lp = reinterpret_cast<const float4*>(g_lin + s * 64 + p * 16);
    float* ap = g_acc + d * 64 + p * 16;
#pragma unroll
    for (int j = 0; j < 4; j++) {
        float4 v = lp[j];
        asm volatile(
            "red.global.add.v4.f32 [%0], {%1, %2, %3, %4};" ::"l"(ap + j * 4),
            "f"(v.x), "f"(v.y), "f"(v.z), "f"(v.w)
            : "memory");
    }
}

// ---------------------------------------------------------------------------
// Final: out = relu( (merge @ W_tr^T + b_tr) + lin - acc/deg )   (deg>0 guard)
// Same GEMM structure with fused epilogue.
// ---------------------------------------------------------------------------
__global__ __launch_bounds__(256) void final_kernel(
    const float* __restrict__ M, const float* __restrict__ W,
    const float* __restrict__ b, float* __restrict__ out, int n) {
    __shared__ float s_x[64 * 68];
    __shared__ float s_w[64 * 68];
    __shared__ float s_b[64];

    int t = threadIdx.x;
    int row0 = blockIdx.x * 64;

    for (int i = t; i < 64 * 64; i += 256) {
        int r = i >> 6, k = i & 63;
        int gr = row0 + r;
        s_x[k * 68 + r] = (gr < n) ? M[gr * 64 + k] : 0.f;
    }
    for (int i = t; i < 64 * 64; i += 256) {
        int c = i >> 6, k = i & 63;
        s_w[k * 68 + c] = W[c * 64 + k];
    }
    if (t < 64) s_b[t] = b[t];
    __syncthreads();

    int tx = t & 15, ty = t >> 4;
    float acc[4][4];
#pragma unroll
    for (int i = 0; i < 4; i++)
#pragma unroll
        for (int j = 0; j < 4; j++) acc[i][j] = 0.f;

#pragma unroll 8
    for (int k = 0; k < 64; k++) {
        float4 xv = *reinterpret_cast<const float4*>(&s_x[k * 68 + ty * 4]);
        float4 wv = *reinterpret_cast<const float4*>(&s_w[k * 68 + tx * 4]);
        float xs[4] = {xv.x, xv.y, xv.z, xv.w};
        float ws[4] = {wv.x, wv.y, wv.z, wv.w};
#pragma unroll
        for (int i = 0; i < 4; i++)
#pragma unroll
            for (int j = 0; j < 4; j++) acc[i][j] = fmaf(xs[i], ws[j], acc[i][j]);
    }

#pragma unroll
    for (int i = 0; i < 4; i++) {
        int gr = row0 + ty * 4 + i;
        if (gr < n) {
            float degv = g_deg[gr];
            float inv = (degv > 0.f) ? (1.0f / degv) : 0.0f;
#pragma unroll
            for (int j = 0; j < 4; j++) {
                int c = tx * 4 + j;
                int idx = gr * 64 + c;
                float v = acc[i][j] + s_b[c] + g_lin[idx] - g_acc[idx] * inv;
                out[idx] = fmaxf(v, 0.0f);
            }
        }
    }
}

// ---------------------------------------------------------------------------
// Launch
// Inputs (metadata order): data[N*64], merge[N*64], src_idx[E], tgt_idx[E],
//                          W_lin[64*64], b_lin[64], W_tr[64*64], b_tr[64]
// Output: float [N*64]
// ---------------------------------------------------------------------------
extern "C" void kernel_launch(void* const* d_in, const int* in_sizes, int n_in,
                              void* d_out, int out_size) {
    const float* data  = (const float*)d_in[0];
    const float* merge = (const float*)d_in[1];
    const int*   src   = (const int*)d_in[2];
    const int*   tgt   = (const int*)d_in[3];
    const float* W_lin = (const float*)d_in[4];
    const float* b_lin = (const float*)d_in[5];
    const float* W_tr  = (const float*)d_in[6];
    const float* b_tr  = (const float*)d_in[7];
    float* out = (float*)d_out;

    int n = in_sizes[0] / D;      // 50000
    int E = in_sizes[2];          // 800000

    int gemm_blocks = (n + 63) / 64;

    zero_kernel<<<592, 256>>>(n);
    gemm_lin_kernel<<<gemm_blocks, 256>>>(data, W_lin, b_lin, n);
    {
        long long threads = (long long)E * 4;
        int blocks = (int)((threads + 255) / 256);
        scatter_kernel<<<blocks, 256>>>(src, tgt, E);
    }
    final_kernel<<<gemm_blocks, 256>>>(merge, W_tr, b_tr, out, n);
}

// round 4
// speedup vs baseline: 1.4053x; 1.4053x over previous
#include <cuda_runtime.h>

#define MAX_NODES 50000
#define MAX_EDGES 800000
#define D 64

// ---------------------------------------------------------------------------
// Scratch (device globals; no allocation allowed)
// ---------------------------------------------------------------------------
__device__ float g_lin[MAX_NODES * D];   // data @ W_lin^T + b_lin
__device__ float g_lap[MAX_NODES * D];   // lin - (sum_src lin)/deg  (0 if deg==0)
__device__ int   g_deg[MAX_NODES];       // in-degree counts
__device__ int   g_off[MAX_NODES];       // CSR row offsets (exclusive prefix)
__device__ int   g_cur[MAX_NODES];       // atomic fill cursors
__device__ int   g_csum[64];             // per-chunk sums for scan
__device__ int   g_coff[64];             // per-chunk exclusive offsets
__device__ int   g_elist[MAX_EDGES];     // src node id per CSR slot

// ---------------------------------------------------------------------------
// CSR build: zero -> count -> scan (3 stages) -> fill
// ---------------------------------------------------------------------------
__global__ void zero_deg_kernel(int n) {
    int i = blockIdx.x * blockDim.x + threadIdx.x;
    if (i < n) g_deg[i] = 0;
}

__global__ void count_kernel(const int* __restrict__ tgt, int E) {
    int e = blockIdx.x * blockDim.x + threadIdx.x;
    if (e < E) atomicAdd(&g_deg[tgt[e]], 1);
}

// Block-level exclusive scan over 1024-element chunks.
__global__ __launch_bounds__(1024) void scanA_kernel(int n) {
    __shared__ int sh[1024];
    int t = threadIdx.x;
    int gid = blockIdx.x * 1024 + t;
    int v = (gid < n) ? g_deg[gid] : 0;
    sh[t] = v;
    __syncthreads();
#pragma unroll
    for (int s = 1; s < 1024; s <<= 1) {
        int a = (t >= s) ? sh[t - s] : 0;
        __syncthreads();
        sh[t] += a;
        __syncthreads();
    }
    if (gid < n) g_off[gid] = sh[t] - v;            // exclusive within chunk
    if (t == 1023) g_csum[blockIdx.x] = sh[1023];   // chunk total
}

// Scan the (<=49) chunk sums.
__global__ void scanB_kernel(int nchunk) {
    __shared__ int sh[64];
    int t = threadIdx.x;   // 64 threads
    int v = (t < nchunk) ? g_csum[t] : 0;
    sh[t] = v;
    __syncthreads();
#pragma unroll
    for (int s = 1; s < 64; s <<= 1) {
        int a = (t >= s) ? sh[t - s] : 0;
        __syncthreads();
        sh[t] += a;
        __syncthreads();
    }
    if (t < 64) g_coff[t] = sh[t] - v;
}

// Add chunk offsets; init fill cursors.
__global__ void scanC_kernel(int n) {
    int i = blockIdx.x * blockDim.x + threadIdx.x;
    if (i < n) {
        int o = g_off[i] + g_coff[i >> 10];
        g_off[i] = o;
        g_cur[i] = o;
    }
}

__global__ void fill_kernel(const int* __restrict__ src,
                            const int* __restrict__ tgt, int E) {
    int e = blockIdx.x * blockDim.x + threadIdx.x;
    if (e < E) {
        int p = atomicAdd(&g_cur[tgt[e]], 1);
        g_elist[p] = src[e];
    }
}

// ---------------------------------------------------------------------------
// GEMM: C = X @ W^T + b.  96x64 block tile, 256 threads.
// Each thread: rows {ty*4..+3} and {64+ty*2..+1}, cols {tx*4..+3}  (24 FMA/k).
// s_x k-major (stride 100), s_w k-major (stride 68): conflict-free main-loop LDS.
// ---------------------------------------------------------------------------
__global__ __launch_bounds__(256) void gemm_lin_kernel(
    const float* __restrict__ X, const float* __restrict__ W,
    const float* __restrict__ b, int n) {
    __shared__ float s_x[64 * 100];
    __shared__ float s_w[64 * 68];
    __shared__ float s_b[64];

    int t = threadIdx.x;
    int row0 = blockIdx.x * 96;

    for (int i = t; i < 96 * 64; i += 256) {
        int r = i >> 6, k = i & 63;
        int gr = row0 + r;
        s_x[k * 100 + r] = (gr < n) ? X[gr * 64 + k] : 0.f;
    }
    for (int i = t; i < 64 * 64; i += 256) {
        int c = i >> 6, k = i & 63;
        s_w[k * 68 + c] = W[c * 64 + k];
    }
    if (t < 64) s_b[t] = b[t];
    __syncthreads();

    int tx = t & 15, ty = t >> 4;
    float accA[4][4], accB[2][4];
#pragma unroll
    for (int i = 0; i < 4; i++)
#pragma unroll
        for (int j = 0; j < 4; j++) accA[i][j] = 0.f;
#pragma unroll
    for (int i = 0; i < 2; i++)
#pragma unroll
        for (int j = 0; j < 4; j++) accB[i][j] = 0.f;

#pragma unroll 8
    for (int k = 0; k < 64; k++) {
        float4 xa = *reinterpret_cast<const float4*>(&s_x[k * 100 + ty * 4]);
        float2 xb = *reinterpret_cast<const float2*>(&s_x[k * 100 + 64 + ty * 2]);
        float4 wv = *reinterpret_cast<const float4*>(&s_w[k * 68 + tx * 4]);
        float xsA[4] = {xa.x, xa.y, xa.z, xa.w};
        float xsB[2] = {xb.x, xb.y};
        float ws[4] = {wv.x, wv.y, wv.z, wv.w};
#pragma unroll
        for (int i = 0; i < 4; i++)
#pragma unroll
            for (int j = 0; j < 4; j++) accA[i][j] = fmaf(xsA[i], ws[j], accA[i][j]);
#pragma unroll
        for (int i = 0; i < 2; i++)
#pragma unroll
            for (int j = 0; j < 4; j++) accB[i][j] = fmaf(xsB[i], ws[j], accB[i][j]);
    }

#pragma unroll
    for (int i = 0; i < 4; i++) {
        int gr = row0 + ty * 4 + i;
        if (gr < n) {
#pragma unroll
            for (int j = 0; j < 4; j++) {
                int c = tx * 4 + j;
                g_lin[gr * 64 + c] = accA[i][j] + s_b[c];
            }
        }
    }
#pragma unroll
    for (int i = 0; i < 2; i++) {
        int gr = row0 + 64 + ty * 2 + i;
        if (gr < n) {
#pragma unroll
            for (int j = 0; j < 4; j++) {
                int c = tx * 4 + j;
                g_lin[gr * 64 + c] = accB[i][j] + s_b[c];
            }
        }
    }
}

// ---------------------------------------------------------------------------
// Gather: warp per node. lap = lin[i] - (sum_{src in list} lin[src]) / deg,
// or 0 when deg == 0. Pure reads (L2-resident), no float atomics.
// ---------------------------------------------------------------------------
__global__ __launch_bounds__(256) void gather_kernel(int n, int E) {
    int w = (blockIdx.x * 256 + threadIdx.x) >> 5;
    int lane = threadIdx.x & 31;
    if (w >= n) return;

    int beg = g_off[w];
    int end = (w + 1 < n) ? g_off[w + 1] : E;
    int col = lane * 2;

    float sx = 0.f, sy = 0.f;
    int j = beg;
    for (; j + 4 <= end; j += 4) {
        int s0 = g_elist[j];
        int s1 = g_elist[j + 1];
        int s2 = g_elist[j + 2];
        int s3 = g_elist[j + 3];
        float2 v0 = *reinterpret_cast<const float2*>(g_lin + s0 * 64 + col);
        float2 v1 = *reinterpret_cast<const float2*>(g_lin + s1 * 64 + col);
        float2 v2 = *reinterpret_cast<const float2*>(g_lin + s2 * 64 + col);
        float2 v3 = *reinterpret_cast<const float2*>(g_lin + s3 * 64 + col);
        sx += v0.x + v1.x + v2.x + v3.x;
        sy += v0.y + v1.y + v2.y + v3.y;
    }
    for (; j < end; j++) {
        int s = g_elist[j];
        float2 v = *reinterpret_cast<const float2*>(g_lin + s * 64 + col);
        sx += v.x;
        sy += v.y;
    }

    int deg = end - beg;
    float2 outv;
    if (deg > 0) {
        float inv = 1.f / (float)deg;
        float2 lv = *reinterpret_cast<const float2*>(g_lin + w * 64 + col);
        outv.x = lv.x - sx * inv;
        outv.y = lv.y - sy * inv;
    } else {
        outv.x = 0.f;
        outv.y = 0.f;
    }
    *reinterpret_cast<float2*>(g_lap + w * 64 + col) = outv;
}

// ---------------------------------------------------------------------------
// Final: out = relu( (merge @ W_tr^T + b_tr) + lap ).  Same GEMM structure.
// ---------------------------------------------------------------------------
__global__ __launch_bounds__(256) void final_kernel(
    const float* __restrict__ M, const float* __restrict__ W,
    const float* __restrict__ b, float* __restrict__ out, int n) {
    __shared__ float s_x[64 * 100];
    __shared__ float s_w[64 * 68];
    __shared__ float s_b[64];

    int t = threadIdx.x;
    int row0 = blockIdx.x * 96;

    for (int i = t; i < 96 * 64; i += 256) {
        int r = i >> 6, k = i & 63;
        int gr = row0 + r;
        s_x[k * 100 + r] = (gr < n) ? M[gr * 64 + k] : 0.f;
    }
    for (int i = t; i < 64 * 64; i += 256) {
        int c = i >> 6, k = i & 63;
        s_w[k * 68 + c] = W[c * 64 + k];
    }
    if (t < 64) s_b[t] = b[t];
    __syncthreads();

    int tx = t & 15, ty = t >> 4;
    float accA[4][4], accB[2][4];
#pragma unroll
    for (int i = 0; i < 4; i++)
#pragma unroll
        for (int j = 0; j < 4; j++) accA[i][j] = 0.f;
#pragma unroll
    for (int i = 0; i < 2; i++)
#pragma unroll
        for (int j = 0; j < 4; j++) accB[i][j] = 0.f;

#pragma unroll 8
    for (int k = 0; k < 64; k++) {
        float4 xa = *reinterpret_cast<const float4*>(&s_x[k * 100 + ty * 4]);
        float2 xb = *reinterpret_cast<const float2*>(&s_x[k * 100 + 64 + ty * 2]);
        float4 wv = *reinterpret_cast<const float4*>(&s_w[k * 68 + tx * 4]);
        float xsA[4] = {xa.x, xa.y, xa.z, xa.w};
        float xsB[2] = {xb.x, xb.y};
        float ws[4] = {wv.x, wv.y, wv.z, wv.w};
#pragma unroll
        for (int i = 0; i < 4; i++)
#pragma unroll
            for (int j = 0; j < 4; j++) accA[i][j] = fmaf(xsA[i], ws[j], accA[i][j]);
#pragma unroll
        for (int i = 0; i < 2; i++)
#pragma unroll
            for (int j = 0; j < 4; j++) accB[i][j] = fmaf(xsB[i], ws[j], accB[i][j]);
    }

#pragma unroll
    for (int i = 0; i < 4; i++) {
        int gr = row0 + ty * 4 + i;
        if (gr < n) {
#pragma unroll
            for (int j = 0; j < 4; j++) {
                int c = tx * 4 + j;
                int idx = gr * 64 + c;
                float v = accA[i][j] + s_b[c] + g_lap[idx];
                out[idx] = fmaxf(v, 0.f);
            }
        }
    }
#pragma unroll
    for (int i = 0; i < 2; i++) {
        int gr = row0 + 64 + ty * 2 + i;
        if (gr < n) {
#pragma unroll
            for (int j = 0; j < 4; j++) {
                int c = tx * 4 + j;
                int idx = gr * 64 + c;
                float v = accB[i][j] + s_b[c] + g_lap[idx];
                out[idx] = fmaxf(v, 0.f);
            }
        }
    }
}

// ---------------------------------------------------------------------------
// Launch
// Inputs: data[N*64], merge[N*64], src_idx[E], tgt_idx[E],
//         W_lin[64*64], b_lin[64], W_tr[64*64], b_tr[64].  Output: float[N*64]
// ---------------------------------------------------------------------------
extern "C" void kernel_launch(void* const* d_in, const int* in_sizes, int n_in,
                              void* d_out, int out_size) {
    const float* data  = (const float*)d_in[0];
    const float* merge = (const float*)d_in[1];
    const int*   src   = (const int*)d_in[2];
    const int*   tgt   = (const int*)d_in[3];
    const float* W_lin = (const float*)d_in[4];
    const float* b_lin = (const float*)d_in[5];
    const float* W_tr  = (const float*)d_in[6];
    const float* b_tr  = (const float*)d_in[7];
    float* out = (float*)d_out;

    int n = in_sizes[0] / D;       // 50000
    int E = in_sizes[2];           // 800000
    int nchunk = (n + 1023) >> 10;
    int gemm_blocks = (n + 95) / 96;

    zero_deg_kernel<<<(n + 255) / 256, 256>>>(n);
    count_kernel<<<(E + 255) / 256, 256>>>(tgt, E);
    scanA_kernel<<<nchunk, 1024>>>(n);
    scanB_kernel<<<1, 64>>>(nchunk);
    scanC_kernel<<<(n + 255) / 256, 256>>>(n);
    fill_kernel<<<(E + 255) / 256, 256>>>(src, tgt, E);

    gemm_lin_kernel<<<gemm_blocks, 256>>>(data, W_lin, b_lin, n);
    gather_kernel<<<(n + 7) / 8, 256>>>(n, E);
    final_kernel<<<gemm_blocks, 256>>>(merge, W_tr, b_tr, out, n);
}